// round 15
// baseline (speedup 1.0000x reference)
#include <cuda_runtime.h>
#include <cuda_bf16.h>
#include <cstdint>

#define NENT  100000
#define BATCH 512
#define DD    200
#define FCIN  10368
#define NCH   32
#define EPSBN 1e-5f
#define KPAD  216            // padded K stride for X image (432B rows)

// g_conv is CHANNEL-MAJOR: element (b, c, p) at [(c*512 + b)*324 + p]
__device__ float          g_conv[(size_t)BATCH * FCIN];
__device__ float          g_fc[DD * BATCH];            // TRANSPOSED: [d*512 + b]
__device__ __nv_bfloat16  g_xb[BATCH * KPAD];          // padded bf16 X image (col200 = 1.0)
__device__ __nv_bfloat16  g_fcb[(size_t)256 * FCIN];   // bf16 fc_w (rows >=200 unused)
__device__ double         g_bn1sum[NCH];
__device__ double         g_bn1sq[NCH];
__device__ double         g_l2[4];
__device__ double         g_loss[3];

// ---------------------------------------------------------------- helpers
__device__ __forceinline__ uint32_t smem_u32(const void* p) {
    uint32_t a;
    asm("{ .reg .u64 t; cvta.to.shared.u64 t, %1; cvt.u32.u64 %0, t; }" : "=r"(a) : "l"(p));
    return a;
}
__device__ __forceinline__ void ldm4(uint32_t* r, uint32_t addr) {
    asm volatile("ldmatrix.sync.aligned.m8n8.x4.shared.b16 {%0,%1,%2,%3}, [%4];"
        : "=r"(r[0]), "=r"(r[1]), "=r"(r[2]), "=r"(r[3]) : "r"(addr));
}
__device__ __forceinline__ void mma16816(float* c, const uint32_t* a, const uint32_t* b) {
    asm volatile("mma.sync.aligned.m16n8k16.row.col.f32.bf16.bf16.f32 "
        "{%0,%1,%2,%3}, {%4,%5,%6,%7}, {%8,%9}, {%0,%1,%2,%3};"
        : "+f"(c[0]), "+f"(c[1]), "+f"(c[2]), "+f"(c[3])
        : "r"(a[0]), "r"(a[1]), "r"(a[2]), "r"(a[3]), "r"(b[0]), "r"(b[1]));
}
#define CP_ASYNC16(dst, src) \
    asm volatile("cp.async.cg.shared.global [%0], [%1], 16;" :: "r"(dst), "l"(src))
#define CP_COMMIT() asm volatile("cp.async.commit_group;" ::: "memory")
#define CP_WAIT0()  asm volatile("cp.async.wait_group 0;" ::: "memory")

__device__ __forceinline__ float warp_red(float v) {
#pragma unroll
    for (int o = 16; o > 0; o >>= 1) v += __shfl_down_sync(0xffffffffu, v, o);
    return v;
}
__device__ __forceinline__ uint32_t bf2pack(float a, float b) {
    return ((uint32_t)__bfloat16_as_ushort(__float2bfloat16_rn(b)) << 16)
         |  (uint32_t)__bfloat16_as_ushort(__float2bfloat16_rn(a));
}
// MUFU softplus (k_psx path)
__device__ __forceinline__ float softplus_fast(float s) {
    float e, l;
    float xn = -fabsf(s) * 1.4426950408889634f;
    asm("ex2.approx.f32 %0, %1;" : "=f"(e) : "f"(xn));
    float arg = 1.0f + e;
    asm("lg2.approx.f32 %0, %1;" : "=f"(l) : "f"(arg));
    return fmaxf(s, 0.0f) + 0.69314718055994531f * l;
}

// ---------------------------------------------------------------- init
__global__ void k_init() {
    int idx = blockIdx.x * blockDim.x + threadIdx.x;
    int stride = gridDim.x * blockDim.x;
    for (int i = idx; i < BATCH * DD; i += stride) g_fc[i] = 0.0f;
    uint32_t* xb = (uint32_t*)g_xb;
    for (int i = idx; i < BATCH * KPAD / 2; i += stride) xb[i] = 0u;
    if (idx < NCH) { g_bn1sum[idx] = 0.0; g_bn1sq[idx] = 0.0; }
    if (idx < 4)   g_l2[idx]  = 0.0;
    if (idx < 3)   g_loss[idx] = 0.0;
}

// ------------------------------------------------- fcw L2 + bf16 convert (float4); conv_w L2
__global__ void k_l2w(const float* __restrict__ fcw, const float* __restrict__ cw) {
    __shared__ float sm[8];
    int t = threadIdx.x;
    float loc = 0.0f;
    const float4* src = (const float4*)fcw;
    const int n4 = DD * FCIN / 4;
    for (int i = blockIdx.x * blockDim.x + t; i < n4; i += gridDim.x * blockDim.x) {
        float4 v = src[i];
        loc = fmaf(v.x, v.x, loc); loc = fmaf(v.y, v.y, loc);
        loc = fmaf(v.z, v.z, loc); loc = fmaf(v.w, v.w, loc);
        *(uint2*)&g_fcb[(size_t)i * 4] = make_uint2(bf2pack(v.x, v.y), bf2pack(v.z, v.w));
    }
    loc = warp_red(loc);
    if ((t & 31) == 0) sm[t >> 5] = loc;
    __syncthreads();
    if (t == 0) {
        float S = 0; for (int i = 0; i < 8; i++) S += sm[i];
        atomicAdd(&g_l2[3], (double)S);
    }
    if (blockIdx.x == 0) {
        __syncthreads();
        float lc = 0.0f;
        if (t < NCH * 9) { float v = cw[t]; lc = v * v; }
        lc = warp_red(lc);
        if ((t & 31) == 0) sm[t >> 5] = lc;
        __syncthreads();
        if (t == 0) {
            float S = 0; for (int i = 0; i < 8; i++) S += sm[i];
            atomicAdd(&g_l2[2], (double)S);
        }
    }
}

// ------------------------------------------------- fused gather + emb L2 + conv + bn1 stats
__global__ void k_conv(const float* __restrict__ ew, const float* __restrict__ rw,
                       const int* __restrict__ h, const int* __restrict__ r,
                       const float* __restrict__ cw, const float* __restrict__ g0p) {
    __shared__ float xn[4][400];
    __shared__ float wts[NCH * 9];
    __shared__ float shh[11], shr[11];
    __shared__ float chs[16], chq[16];
    int b0 = blockIdx.x * 4, t = threadIdx.x;
    int c0 = blockIdx.y * 16;
    float g0 = g0p[0];
    float l2h = 0.0f, l2r = 0.0f;
    for (int i = t; i < 1600; i += 352) {
        int bb = i / 400, pos = i % 400, b = b0 + bb;
        float v;
        if (pos < 200) { v = ew[(size_t)h[b] * DD + pos]; l2h = fmaf(v, v, l2h); }
        else           { v = rw[(size_t)r[b] * DD + (pos - 200)]; l2r = fmaf(v, v, l2r); }
        xn[bb][pos] = g0 * v;
    }
    if (t < NCH * 9) wts[t] = cw[t];
    if (t < 16) { chs[t] = 0.0f; chq[t] = 0.0f; }
    if (blockIdx.y == 0) {
        l2h = warp_red(l2h); l2r = warp_red(l2r);
        if ((t & 31) == 0) { shh[t >> 5] = l2h; shr[t >> 5] = l2r; }
    }
    __syncthreads();
    if (blockIdx.y == 0 && t == 0) {
        float H = 0, R = 0;
        for (int i = 0; i < 11; i++) { H += shh[i]; R += shr[i]; }
        atomicAdd(&g_l2[0], (double)H);
        atomicAdd(&g_l2[1], (double)R);
    }
    bool valid = t < 324;
    int ii = valid ? t / 18 : 0;
    int jj = valid ? t % 18 : 0;
    int boff = ii * 20 + jj;
    for (int c = c0; c < c0 + 16; c++) {
        float s = 0.0f, q = 0.0f;
#pragma unroll
        for (int bb = 0; bb < 4; bb++) {
            const float* base = &xn[bb][boff];
            float acc = 0.0f;
#pragma unroll
            for (int ki = 0; ki < 3; ki++)
#pragma unroll
                for (int kj = 0; kj < 3; kj++)
                    acc = fmaf(base[ki * 20 + kj], wts[c * 9 + ki * 3 + kj], acc);
            if (valid) {
                g_conv[((size_t)c * 512 + b0 + bb) * 324 + t] = acc;
                s += acc;
                q = fmaf(acc, acc, q);
            }
        }
        s = warp_red(s); q = warp_red(q);
        if ((t & 31) == 0) { atomicAdd(&chs[c - c0], s); atomicAdd(&chq[c - c0], q); }
    }
    __syncthreads();
    if (t < 16) {
        atomicAdd(&g_bn1sum[c0 + t], (double)chs[t]);
        atomicAdd(&g_bn1sq[c0 + t],  (double)chq[t]);
    }
}

// ------------------------------------------------- FC via bf16 mma, 64m x 64n tiles (576 CTAs, 3/SM)
__global__ __launch_bounds__(256, 3) void k_fc(const float* __restrict__ g1,
                                               const float* __restrict__ b1) {
    __shared__ __align__(16) char As2[2][64 * 144];
    __shared__ __align__(16) char Bs2[2][64 * 144];
    __shared__ float a_tab[576], b_tab[576];
    __shared__ float a1s[NCH], b1s[NCH];
    uint32_t as0 = smem_u32(As2[0]);
    uint32_t bs0 = smem_u32(Bs2[0]);
    int t = threadIdx.x, lane = t & 31, wid = t >> 5;
    int m0 = blockIdx.x * 64, n0 = blockIdx.y * 64;
    int kseg = blockIdx.z * 576;
    int arow = t >> 2, aq = t & 3;   // A-pack role: 4 threads per row

    // prefetch B chunk 0 into B0 (64 rows x 128B = 512 x 16B ops)
    {
#pragma unroll
        for (int j = 0; j < 2; j++) {
            int u = t + j * 256;
            int row = u >> 3, off = u & 7;
            CP_ASYNC16(bs0 + row * 144 + off * 16,
                       (const char*)&g_fcb[(size_t)(n0 + row) * FCIN + kseg + off * 8]);
        }
        CP_COMMIT();
    }
    // preload raw A regs for chunk 0
    float4 raw[4];
#pragma unroll
    for (int j = 0; j < 4; j++) {
        int k4 = kseg + aq * 16 + j * 4;
        int c = k4 / 324, pp = k4 - c * 324;
        raw[j] = *(const float4*)&g_conv[((size_t)c * 512 + m0 + arow) * 324 + pp];
    }
    // folded k_bn1fin: bn1 affine from raw sums
    if (t < NCH) {
        double cnt = 512.0 * 324.0;
        double mean = g_bn1sum[t] / cnt;
        double var  = g_bn1sq[t] / cnt - mean * mean;
        float a = g1[t] * rsqrtf((float)var + EPSBN);
        a1s[t] = a;
        b1s[t] = b1[t] - (float)mean * a;
    }
    __syncthreads();
    for (int i = t; i < 576; i += 256) {
        int c = (kseg + i) / 324;
        a_tab[i] = a1s[c];
        b_tab[i] = b1s[c];
    }
    __syncthreads();

    int mw = wid >> 2, nw = wid & 3;             // 2 x 4 warp layout
    int m_base = mw * 32, n_base = nw * 16;      // warp tile 32m x 16n
    uint32_t aaddr[2], baddr;
#pragma unroll
    for (int mt = 0; mt < 2; mt++)
        aaddr[mt] = as0 + (uint32_t)(m_base + mt * 16 + (lane & 15)) * 144 + (lane >> 4) * 16;
    baddr = bs0 + (uint32_t)(n_base + (lane >> 4) * 8 + (lane & 7)) * 144
                + ((lane >> 3) & 1) * 16;

    float acc[2][2][4];
#pragma unroll
    for (int i = 0; i < 2; i++)
#pragma unroll
        for (int j = 0; j < 2; j++)
#pragma unroll
            for (int k = 0; k < 4; k++) acc[i][j][k] = 0.0f;

    for (int ch = 0; ch < 9; ch++) {
        int buf = ch & 1;
        int kb = kseg + ch * 64;
        // transform preloaded raw regs -> A[buf]
        {
            char* As = As2[buf];
#pragma unroll
            for (int j = 0; j < 4; j++) {
                int kc = aq * 16 + j * 4;
                int kti = ch * 64 + kc;
                float4 v = raw[j];
                float y0 = fmaxf(fmaf(v.x, a_tab[kti],     b_tab[kti]),     0.0f);
                float y1 = fmaxf(fmaf(v.y, a_tab[kti + 1], b_tab[kti + 1]), 0.0f);
                float y2 = fmaxf(fmaf(v.z, a_tab[kti + 2], b_tab[kti + 2]), 0.0f);
                float y3 = fmaxf(fmaf(v.w, a_tab[kti + 3], b_tab[kti + 3]), 0.0f);
                *(uint2*)&As[arow * 144 + kc * 2] = make_uint2(bf2pack(y0, y1), bf2pack(y2, y3));
            }
        }
        CP_WAIT0();
        __syncthreads();
        if (ch < 8) {
            int kb2 = kb + 64;
#pragma unroll
            for (int j = 0; j < 2; j++) {
                int u = t + j * 256;
                int row = u >> 3, off = u & 7;
                CP_ASYNC16(bs0 + (1 - buf) * 9216 + row * 144 + off * 16,
                           (const char*)&g_fcb[(size_t)(n0 + row) * FCIN + kb2 + off * 8]);
            }
            CP_COMMIT();
            // next raw A regs (LDG latency covered by mma below)
#pragma unroll
            for (int j = 0; j < 4; j++) {
                int k4 = kb2 + aq * 16 + j * 4;
                int c = k4 / 324, pp = k4 - c * 324;
                raw[j] = *(const float4*)&g_conv[((size_t)c * 512 + m0 + arow) * 324 + pp];
            }
        }
        uint32_t off = buf * 9216;
#pragma unroll
        for (int ks = 0; ks < 4; ks++) {
            uint32_t A[2][4], Bf[4];
#pragma unroll
            for (int mt = 0; mt < 2; mt++) ldm4(A[mt], aaddr[mt] + off + ks * 32);
            ldm4(Bf, baddr + off + ks * 32);
#pragma unroll
            for (int mt = 0; mt < 2; mt++)
#pragma unroll
                for (int nt = 0; nt < 2; nt++)
                    mma16816(acc[mt][nt], A[mt], &Bf[nt * 2]);
        }
    }
    // epilogue: atomic accumulate into TRANSPOSED g_fc [d*512 + b]
#pragma unroll
    for (int mt = 0; mt < 2; mt++) {
        int r0 = m0 + m_base + mt * 16 + (lane >> 2);
#pragma unroll
        for (int nt = 0; nt < 2; nt++) {
#pragma unroll
            for (int c2 = 0; c2 < 2; c2++) {
                int d = n0 + n_base + nt * 8 + (lane & 3) * 2 + c2;
                if (d < DD) {
                    atomicAdd(&g_fc[d * 512 + r0],       acc[mt][nt][c2]);
                    atomicAdd(&g_fc[d * 512 + r0 + 8],   acc[mt][nt][2 + c2]);
                }
            }
        }
    }
}

// ------------------------------------------------- bn2 + leaky relu -> padded bf16 X image
__global__ void k_bn2(const float* __restrict__ g2, const float* __restrict__ b2) {
    __shared__ float sms[8], smq[8], par[2];
    int d = blockIdx.x, t = threadIdx.x;
    float y0 = g_fc[d * 512 + t];
    float y1 = g_fc[d * 512 + t + 256];
    float s = y0 + y1;
    float q = fmaf(y0, y0, y1 * y1);
    s = warp_red(s); q = warp_red(q);
    if ((t & 31) == 0) { sms[t >> 5] = s; smq[t >> 5] = q; }
    __syncthreads();
    if (t == 0) {
        float S = 0, Q = 0;
        for (int i = 0; i < 8; i++) { S += sms[i]; Q += smq[i]; }
        float mean = S * (1.0f / 512.0f);
        float var  = Q * (1.0f / 512.0f) - mean * mean;
        float a = g2[d] * rsqrtf(var + EPSBN);
        par[0] = a; par[1] = b2[d] - mean * a;
    }
    __syncthreads();
    float a = par[0], c = par[1];
    float v0 = fmaf(y0, a, c); v0 = v0 > 0.0f ? v0 : 0.01f * v0;
    float v1 = fmaf(y1, a, c); v1 = v1 > 0.0f ? v1 : 0.01f * v1;
    g_xb[t * KPAD + d]         = __float2bfloat16_rn(v0);
    g_xb[(t + 256) * KPAD + d] = __float2bfloat16_rn(v1);
    if (blockIdx.x == 0) {                 // bias-fold column: X[:,200] = 1.0
        g_xb[t * KPAD + 200]         = __float2bfloat16_rn(1.0f);
        g_xb[(t + 256) * KPAD + 200] = __float2bfloat16_rn(1.0f);
    }
}

// ------------------------------------------------- positive-target scores (512 dots)
__global__ void k_psx(const float* __restrict__ ew, const float* __restrict__ bias,
                      const int* __restrict__ pos) {
    __shared__ double acc8[8];
    int b = blockIdx.x * 8 + (threadIdx.x >> 5);
    int lane = threadIdx.x & 31;
    int p = pos[b];
    const float* e = ew + (size_t)p * DD;
    float s = 0.0f;
    for (int d = lane; d < DD; d += 32)
        s = fmaf(__bfloat162float(g_xb[b * KPAD + d]), e[d], s);
    s = warp_red(s);
    if (lane == 0) acc8[threadIdx.x >> 5] = (double)(s + bias[p]);
    __syncthreads();
    if (threadIdx.x == 0) {
        double S = 0;
        for (int i = 0; i < 8; i++) S += acc8[i];
        atomicAdd(&g_loss[2], S);
    }
}

// ------------------------------------------------- scores: E once, cp.async X pipeline
// Quad-merged softplus: one lg2 per 4 scores via product of (1+t_i).
__global__ __launch_bounds__(256, 2)
void k_scores(const float* __restrict__ ew, const float* __restrict__ bias) {
    extern __shared__ char smem[];
    uint32_t xs = smem_u32(smem);            // X tile: 128 x 216 bf16 = 55296B
    uint32_t es = xs + 55296;                // E tile: 128 x 216 bf16 = 55296B
    __shared__ float red[2][8];
    int t = threadIdx.x, lane = t & 31, wid = t >> 5;
    int NB = blockIdx.x * 128;

    {
        const char* src = (const char*)g_xb;
        for (int i = t; i < 3456; i += 256) CP_ASYNC16(xs + i * 16, src + i * 16);
        CP_COMMIT();
    }
    char* esm = smem + 55296;
    for (int idx = t; idx < 6400; idx += 256) {
        int row = idx / 50, q = idx % 50;
        int e = NB + row;
        uint2 w = make_uint2(0u, 0u);
        if (e < NENT) {
            float4 v = *(const float4*)&ew[(size_t)e * DD + q * 4];
            w = make_uint2(bf2pack(v.x, v.y), bf2pack(v.z, v.w));
        }
        *(uint2*)(esm + row * 432 + q * 8) = w;
    }
    for (int idx = t; idx < 512; idx += 256) {
        int row = idx >> 2, c = idx & 3;
        uint32_t w = 0u;
        if (c == 0) {
            int e = NB + row;
            if (e < NENT)
                w = (uint32_t)__bfloat16_as_ushort(__float2bfloat16_rn(bias[e]));
        }
        *(uint32_t*)(esm + row * 432 + 400 + c * 4) = w;
    }
    CP_WAIT0();
    __syncthreads();

    int mw = wid >> 2, nw = wid & 3;
    int m_base = mw * 64, n_base = nw * 32;
    uint32_t aaddr[4], baddr[2];
#pragma unroll
    for (int mt = 0; mt < 4; mt++)
        aaddr[mt] = xs + (uint32_t)(m_base + mt * 16 + (lane & 15)) * 432 + (lane >> 4) * 16;
#pragma unroll
    for (int p = 0; p < 2; p++)
        baddr[p] = es + (uint32_t)(n_base + p * 16 + (lane >> 4) * 8 + (lane & 7)) * 432
                      + ((lane >> 3) & 1) * 16;

    float spx = 0.0f, ssx = 0.0f;
    const float l2e = 1.4426950408889634f;

    for (int r = 0; r < 4; r++) {
        float acc[4][4][4];
#pragma unroll
        for (int i = 0; i < 4; i++)
#pragma unroll
            for (int j = 0; j < 4; j++)
#pragma unroll
                for (int k = 0; k < 4; k++) acc[i][j][k] = 0.0f;

        for (int ks = 0; ks < 13; ks++) {
            uint32_t A[4][4], Bf[2][4];
#pragma unroll
            for (int mt = 0; mt < 4; mt++) ldm4(A[mt], aaddr[mt] + ks * 32);
#pragma unroll
            for (int p = 0; p < 2; p++)   ldm4(Bf[p], baddr[p] + ks * 32);
#pragma unroll
            for (int mt = 0; mt < 4; mt++)
#pragma unroll
                for (int nt = 0; nt < 4; nt++)
                    mma16816(acc[mt][nt], A[mt], &Bf[nt >> 1][(nt & 1) * 2]);
        }
        __syncthreads();

        if (r < 3) {
            const char* src = (const char*)(g_xb + (r + 1) * 128 * KPAD);
            for (int i = t; i < 3456; i += 256) CP_ASYNC16(xs + i * 16, src + i * 16);
            CP_COMMIT();
        }

        // quad-merged epilogue: per (mt,nt) 4 scores -> 4 ex2 + 1 lg2
#pragma unroll
        for (int mt = 0; mt < 4; mt++)
#pragma unroll
            for (int nt = 0; nt < 4; nt++) {
                float s0 = acc[mt][nt][0], s1 = acc[mt][nt][1];
                float s2 = acc[mt][nt][2], s3 = acc[mt][nt][3];
                ssx += (s0 + s1) + (s2 + s3);
                float t0, t1, t2, t3, lg;
                asm("ex2.approx.f32 %0, %1;" : "=f"(t0) : "f"(-fabsf(s0) * l2e));
                asm("ex2.approx.f32 %0, %1;" : "=f"(t1) : "f"(-fabsf(s1) * l2e));
                asm("ex2.approx.f32 %0, %1;" : "=f"(t2) : "f"(-fabsf(s2) * l2e));
                asm("ex2.approx.f32 %0, %1;" : "=f"(t3) : "f"(-fabsf(s3) * l2e));
                float pr = ((1.0f + t0) * (1.0f + t1)) * ((1.0f + t2) * (1.0f + t3));
                asm("lg2.approx.f32 %0, %1;" : "=f"(lg) : "f"(pr));
                spx += ((fmaxf(s0, 0.0f) + fmaxf(s1, 0.0f))
                      + (fmaxf(s2, 0.0f) + fmaxf(s3, 0.0f)))
                     + 0.69314718055994531f * lg;
            }
        if (r < 3) { CP_WAIT0(); __syncthreads(); }
    }

    spx = warp_red(spx); ssx = warp_red(ssx);
    if (lane == 0) { red[0][wid] = spx; red[1][wid] = ssx; }
    __syncthreads();
    if (t == 0) {
        float SP = 0, SS = 0;
        for (int i = 0; i < 8; i++) { SP += red[0][i]; SS += red[1][i]; }
        atomicAdd(&g_loss[0], (double)SP);
        atomicAdd(&g_loss[1], (double)SS);
    }
}

// ------------------------------------------------- final combine
__global__ void k_final(float* out) {
    double sp = g_loss[0], ss = g_loss[1], ps = g_loss[2];
    // 96 phantom entity rows x 512 batches contribute softplus(0)=ln2 each
    double corr = 49152.0 * 0.69314718055994531;
    double kg = (sp - corr - ss / (double)NENT - 0.9 * ps) / ((double)BATCH * (double)NENT);
    double l2 = g_l2[0] / (2.0 * 512.0 * 200.0)
              + g_l2[1] / (2.0 * 512.0 * 200.0)
              + g_l2[2] / (2.0 * 288.0)
              + g_l2[3] / (2.0 * 200.0);
    out[0] = (float)(kg + 1e-5 * l2);
}

extern "C" void kernel_launch(void* const* d_in, const int* in_sizes, int n_in,
                              void* d_out, int out_size) {
    const float* ew   = (const float*)d_in[0];
    const float* rw   = (const float*)d_in[1];
    const float* cw   = (const float*)d_in[2];
    const float* fcw  = (const float*)d_in[4];
    const float* bias = (const float*)d_in[6];
    const float* g0   = (const float*)d_in[7];
    const float* g1   = (const float*)d_in[9];
    const float* b1   = (const float*)d_in[10];
    const float* g2   = (const float*)d_in[11];
    const float* b2   = (const float*)d_in[12];
    const int*   h    = (const int*)d_in[13];
    const int*   r    = (const int*)d_in[14];
    const int*   pos  = (const int*)d_in[15];

    const int SMEM_SC = 2 * 55296;
    cudaFuncSetAttribute(k_scores, cudaFuncAttributeMaxDynamicSharedMemorySize, SMEM_SC);

    k_init<<<200, 256>>>();
    k_l2w<<<256, 256>>>(fcw, cw);
    k_conv<<<dim3(128, 2), 352>>>(ew, rw, h, r, cw, g0);
    k_fc<<<dim3(8, 4, 18), 256>>>(g1, b1);
    k_bn2<<<200, 256>>>(g2, b2);
    k_psx<<<64, 256>>>(ew, bias, pos);
    k_scores<<<782, 256, SMEM_SC>>>(ew, bias);
    k_final<<<1, 1>>>((float*)d_out);
}

// round 16
// speedup vs baseline: 1.1270x; 1.1270x over previous
#include <cuda_runtime.h>
#include <cuda_bf16.h>
#include <cstdint>

#define NENT  100000
#define BATCH 512
#define DD    200
#define FCIN  10368
#define NCH   32
#define EPSBN 1e-5f
#define KPAD  216            // padded K stride for X image (432B rows)

// g_conv is CHANNEL-MAJOR: element (b, c, p) at [(c*512 + b)*324 + p]
__device__ float          g_conv[(size_t)BATCH * FCIN];
__device__ float          g_fc[DD * BATCH];            // TRANSPOSED: [d*512 + b]
__device__ __nv_bfloat16  g_xb[BATCH * KPAD];          // padded bf16 X image (col200 = 1.0)
__device__ __nv_bfloat16  g_fcb[(size_t)256 * FCIN];   // bf16 fc_w (rows >=200 unused)
__device__ double         g_bn1sum[NCH];
__device__ double         g_bn1sq[NCH];
__device__ double         g_l2[4];
__device__ double         g_loss[3];

// ---------------------------------------------------------------- helpers
__device__ __forceinline__ uint32_t smem_u32(const void* p) {
    uint32_t a;
    asm("{ .reg .u64 t; cvta.to.shared.u64 t, %1; cvt.u32.u64 %0, t; }" : "=r"(a) : "l"(p));
    return a;
}
__device__ __forceinline__ void ldm4(uint32_t* r, uint32_t addr) {
    asm volatile("ldmatrix.sync.aligned.m8n8.x4.shared.b16 {%0,%1,%2,%3}, [%4];"
        : "=r"(r[0]), "=r"(r[1]), "=r"(r[2]), "=r"(r[3]) : "r"(addr));
}
__device__ __forceinline__ void mma16816(float* c, const uint32_t* a, const uint32_t* b) {
    asm volatile("mma.sync.aligned.m16n8k16.row.col.f32.bf16.bf16.f32 "
        "{%0,%1,%2,%3}, {%4,%5,%6,%7}, {%8,%9}, {%0,%1,%2,%3};"
        : "+f"(c[0]), "+f"(c[1]), "+f"(c[2]), "+f"(c[3])
        : "r"(a[0]), "r"(a[1]), "r"(a[2]), "r"(a[3]), "r"(b[0]), "r"(b[1]));
}
#define CP_ASYNC16(dst, src) \
    asm volatile("cp.async.cg.shared.global [%0], [%1], 16;" :: "r"(dst), "l"(src))
#define CP_COMMIT() asm volatile("cp.async.commit_group;" ::: "memory")
#define CP_WAIT0()  asm volatile("cp.async.wait_group 0;" ::: "memory")

__device__ __forceinline__ float warp_red(float v) {
#pragma unroll
    for (int o = 16; o > 0; o >>= 1) v += __shfl_down_sync(0xffffffffu, v, o);
    return v;
}
__device__ __forceinline__ uint32_t bf2pack(float a, float b) {
    return ((uint32_t)__bfloat16_as_ushort(__float2bfloat16_rn(b)) << 16)
         |  (uint32_t)__bfloat16_as_ushort(__float2bfloat16_rn(a));
}
// MUFU softplus (k_psx path)
__device__ __forceinline__ float softplus_fast(float s) {
    float e, l;
    float xn = -fabsf(s) * 1.4426950408889634f;
    asm("ex2.approx.f32 %0, %1;" : "=f"(e) : "f"(xn));
    float arg = 1.0f + e;
    asm("lg2.approx.f32 %0, %1;" : "=f"(l) : "f"(arg));
    return fmaxf(s, 0.0f) + 0.69314718055994531f * l;
}

// ---------------------------------------------------------------- init
__global__ void k_init() {
    int idx = blockIdx.x * blockDim.x + threadIdx.x;
    int stride = gridDim.x * blockDim.x;
    for (int i = idx; i < BATCH * DD; i += stride) g_fc[i] = 0.0f;
    uint32_t* xb = (uint32_t*)g_xb;
    for (int i = idx; i < BATCH * KPAD / 2; i += stride) xb[i] = 0u;
    if (idx < NCH) { g_bn1sum[idx] = 0.0; g_bn1sq[idx] = 0.0; }
    if (idx < 4)   g_l2[idx]  = 0.0;
    if (idx < 3)   g_loss[idx] = 0.0;
}

// ------------------------------------------------- fcw L2 + bf16 convert (float4); conv_w L2
__global__ void k_l2w(const float* __restrict__ fcw, const float* __restrict__ cw) {
    __shared__ float sm[8];
    int t = threadIdx.x;
    float loc = 0.0f;
    const float4* src = (const float4*)fcw;
    const int n4 = DD * FCIN / 4;
    for (int i = blockIdx.x * blockDim.x + t; i < n4; i += gridDim.x * blockDim.x) {
        float4 v = src[i];
        loc = fmaf(v.x, v.x, loc); loc = fmaf(v.y, v.y, loc);
        loc = fmaf(v.z, v.z, loc); loc = fmaf(v.w, v.w, loc);
        *(uint2*)&g_fcb[(size_t)i * 4] = make_uint2(bf2pack(v.x, v.y), bf2pack(v.z, v.w));
    }
    loc = warp_red(loc);
    if ((t & 31) == 0) sm[t >> 5] = loc;
    __syncthreads();
    if (t == 0) {
        float S = 0; for (int i = 0; i < 8; i++) S += sm[i];
        atomicAdd(&g_l2[3], (double)S);
    }
    if (blockIdx.x == 0) {
        __syncthreads();
        float lc = 0.0f;
        if (t < NCH * 9) { float v = cw[t]; lc = v * v; }
        lc = warp_red(lc);
        if ((t & 31) == 0) sm[t >> 5] = lc;
        __syncthreads();
        if (t == 0) {
            float S = 0; for (int i = 0; i < 8; i++) S += sm[i];
            atomicAdd(&g_l2[2], (double)S);
        }
    }
}

// ------------------------------------------------- fused gather + emb L2 + conv + bn1 stats
// grid (64, 2): x = 8-batch group, y = 16-channel half.
__global__ void k_conv(const float* __restrict__ ew, const float* __restrict__ rw,
                       const int* __restrict__ h, const int* __restrict__ r,
                       const float* __restrict__ cw, const float* __restrict__ g0p) {
    __shared__ float xn[8][400];
    __shared__ float wts[NCH * 9];
    __shared__ float shh[11], shr[11];
    __shared__ float chs[16], chq[16];
    int b0 = blockIdx.x * 8, t = threadIdx.x;
    int c0 = blockIdx.y * 16;
    float g0 = g0p[0];
    float l2h = 0.0f, l2r = 0.0f;
    for (int i = t; i < 3200; i += 352) {
        int bb = i / 400, pos = i % 400, b = b0 + bb;
        float v;
        if (pos < 200) { v = ew[(size_t)h[b] * DD + pos]; l2h = fmaf(v, v, l2h); }
        else           { v = rw[(size_t)r[b] * DD + (pos - 200)]; l2r = fmaf(v, v, l2r); }
        xn[bb][pos] = g0 * v;
    }
    if (t < NCH * 9) wts[t] = cw[t];
    if (t < 16) { chs[t] = 0.0f; chq[t] = 0.0f; }
    if (blockIdx.y == 0) {
        l2h = warp_red(l2h); l2r = warp_red(l2r);
        if ((t & 31) == 0) { shh[t >> 5] = l2h; shr[t >> 5] = l2r; }
    }
    __syncthreads();
    if (blockIdx.y == 0 && t == 0) {
        float H = 0, R = 0;
        for (int i = 0; i < 11; i++) { H += shh[i]; R += shr[i]; }
        atomicAdd(&g_l2[0], (double)H);
        atomicAdd(&g_l2[1], (double)R);
    }
    bool valid = t < 324;
    int ii = valid ? t / 18 : 0;
    int jj = valid ? t % 18 : 0;
    int boff = ii * 20 + jj;
    for (int c = c0; c < c0 + 16; c++) {
        float s = 0.0f, q = 0.0f;
#pragma unroll
        for (int bb = 0; bb < 8; bb++) {
            const float* base = &xn[bb][boff];
            float acc = 0.0f;
#pragma unroll
            for (int ki = 0; ki < 3; ki++)
#pragma unroll
                for (int kj = 0; kj < 3; kj++)
                    acc = fmaf(base[ki * 20 + kj], wts[c * 9 + ki * 3 + kj], acc);
            if (valid) {
                g_conv[((size_t)c * 512 + b0 + bb) * 324 + t] = acc;
                s += acc;
                q = fmaf(acc, acc, q);
            }
        }
        s = warp_red(s); q = warp_red(q);
        if ((t & 31) == 0) { atomicAdd(&chs[c - c0], s); atomicAdd(&chq[c - c0], q); }
    }
    __syncthreads();
    if (t < 16) {
        atomicAdd(&g_bn1sum[c0 + t], (double)chs[t]);
        atomicAdd(&g_bn1sq[c0 + t],  (double)chq[t]);
    }
}

// ------------------------------------------------- FC via bf16 mma, register-pipelined A loads
// (R14 shape: 64m x 128n x 576k tiles, 288 CTAs, 2 CTAs/SM)
__global__ __launch_bounds__(256, 2) void k_fc(const float* __restrict__ g1,
                                               const float* __restrict__ b1) {
    __shared__ __align__(16) char As2[2][64 * 144];
    __shared__ __align__(16) char Bs2[2][128 * 144];
    __shared__ float a_tab[576], b_tab[576];
    __shared__ float a1s[NCH], b1s[NCH];
    uint32_t as0 = smem_u32(As2[0]);
    uint32_t bs0 = smem_u32(Bs2[0]);
    int t = threadIdx.x, lane = t & 31, wid = t >> 5;
    int m0 = blockIdx.x * 64, n0 = blockIdx.y * 128;
    int kseg = blockIdx.z * 576;
    int arow = t >> 2, aq = t & 3;   // A-pack role: 4 threads per row

    // prefetch B chunk 0 into B0
    {
#pragma unroll
        for (int j = 0; j < 4; j++) {
            int u = t + j * 256;
            int row = u >> 3, off = u & 7;
            CP_ASYNC16(bs0 + row * 144 + off * 16,
                       (const char*)&g_fcb[(size_t)(n0 + row) * FCIN + kseg + off * 8]);
        }
        CP_COMMIT();
    }
    // preload raw A regs for chunk 0
    float4 raw[4];
#pragma unroll
    for (int j = 0; j < 4; j++) {
        int k4 = kseg + aq * 16 + j * 4;
        int c = k4 / 324, pp = k4 - c * 324;
        raw[j] = *(const float4*)&g_conv[((size_t)c * 512 + m0 + arow) * 324 + pp];
    }
    // folded k_bn1fin: bn1 affine from raw sums
    if (t < NCH) {
        double cnt = 512.0 * 324.0;
        double mean = g_bn1sum[t] / cnt;
        double var  = g_bn1sq[t] / cnt - mean * mean;
        float a = g1[t] * rsqrtf((float)var + EPSBN);
        a1s[t] = a;
        b1s[t] = b1[t] - (float)mean * a;
    }
    __syncthreads();
    for (int i = t; i < 576; i += 256) {
        int c = (kseg + i) / 324;
        a_tab[i] = a1s[c];
        b_tab[i] = b1s[c];
    }
    __syncthreads();

    int mw = wid >> 2, nw = wid & 3;             // 2 x 4 warp layout
    int m_base = mw * 32, n_base = nw * 32;      // warp tile 32m x 32n
    uint32_t aaddr[2], baddr[2];
#pragma unroll
    for (int mt = 0; mt < 2; mt++)
        aaddr[mt] = as0 + (uint32_t)(m_base + mt * 16 + (lane & 15)) * 144 + (lane >> 4) * 16;
#pragma unroll
    for (int p = 0; p < 2; p++)
        baddr[p] = bs0 + (uint32_t)(n_base + p * 16 + (lane >> 4) * 8 + (lane & 7)) * 144
                       + ((lane >> 3) & 1) * 16;

    float acc[2][4][4];
#pragma unroll
    for (int i = 0; i < 2; i++)
#pragma unroll
        for (int j = 0; j < 4; j++)
#pragma unroll
            for (int k = 0; k < 4; k++) acc[i][j][k] = 0.0f;

    for (int ch = 0; ch < 9; ch++) {
        int buf = ch & 1;
        int kb = kseg + ch * 64;
        // transform preloaded raw regs -> A[buf]
        {
            char* As = As2[buf];
#pragma unroll
            for (int j = 0; j < 4; j++) {
                int kc = aq * 16 + j * 4;
                int kti = ch * 64 + kc;
                float4 v = raw[j];
                float y0 = fmaxf(fmaf(v.x, a_tab[kti],     b_tab[kti]),     0.0f);
                float y1 = fmaxf(fmaf(v.y, a_tab[kti + 1], b_tab[kti + 1]), 0.0f);
                float y2 = fmaxf(fmaf(v.z, a_tab[kti + 2], b_tab[kti + 2]), 0.0f);
                float y3 = fmaxf(fmaf(v.w, a_tab[kti + 3], b_tab[kti + 3]), 0.0f);
                *(uint2*)&As[arow * 144 + kc * 2] = make_uint2(bf2pack(y0, y1), bf2pack(y2, y3));
            }
        }
        CP_WAIT0();
        __syncthreads();
        if (ch < 8) {
            int kb2 = kb + 64;
            // next B tile (async)
#pragma unroll
            for (int j = 0; j < 4; j++) {
                int u = t + j * 256;
                int row = u >> 3, off = u & 7;
                CP_ASYNC16(bs0 + (1 - buf) * 18432 + row * 144 + off * 16,
                           (const char*)&g_fcb[(size_t)(n0 + row) * FCIN + kb2 + off * 8]);
            }
            CP_COMMIT();
            // next raw A regs (LDG latency covered by the mma stage below)
#pragma unroll
            for (int j = 0; j < 4; j++) {
                int k4 = kb2 + aq * 16 + j * 4;
                int c = k4 / 324, pp = k4 - c * 324;
                raw[j] = *(const float4*)&g_conv[((size_t)c * 512 + m0 + arow) * 324 + pp];
            }
        }
        uint32_t ao = buf * 9216, bo = buf * 18432;
#pragma unroll
        for (int ks = 0; ks < 4; ks++) {
            uint32_t A[2][4], Bf[2][4];
#pragma unroll
            for (int mt = 0; mt < 2; mt++) ldm4(A[mt], aaddr[mt] + ao + ks * 32);
#pragma unroll
            for (int p = 0; p < 2; p++)   ldm4(Bf[p], baddr[p] + bo + ks * 32);
#pragma unroll
            for (int mt = 0; mt < 2; mt++)
#pragma unroll
                for (int nt = 0; nt < 4; nt++)
                    mma16816(acc[mt][nt], A[mt], &Bf[nt >> 1][(nt & 1) * 2]);
        }
    }
    // epilogue: atomic accumulate into TRANSPOSED g_fc [d*512 + b]
#pragma unroll
    for (int mt = 0; mt < 2; mt++) {
        int r0 = m0 + m_base + mt * 16 + (lane >> 2);
#pragma unroll
        for (int nt = 0; nt < 4; nt++) {
#pragma unroll
            for (int c2 = 0; c2 < 2; c2++) {
                int d = n0 + n_base + nt * 8 + (lane & 3) * 2 + c2;
                if (d < DD) {
                    atomicAdd(&g_fc[d * 512 + r0],       acc[mt][nt][c2]);
                    atomicAdd(&g_fc[d * 512 + r0 + 8],   acc[mt][nt][2 + c2]);
                }
            }
        }
    }
}

// ------------------------------------------------- bn2 + leaky relu -> padded bf16 X image
__global__ void k_bn2(const float* __restrict__ g2, const float* __restrict__ b2) {
    __shared__ float sms[8], smq[8], par[2];
    int d = blockIdx.x, t = threadIdx.x;
    float y0 = g_fc[d * 512 + t];
    float y1 = g_fc[d * 512 + t + 256];
    float s = y0 + y1;
    float q = fmaf(y0, y0, y1 * y1);
    s = warp_red(s); q = warp_red(q);
    if ((t & 31) == 0) { sms[t >> 5] = s; smq[t >> 5] = q; }
    __syncthreads();
    if (t == 0) {
        float S = 0, Q = 0;
        for (int i = 0; i < 8; i++) { S += sms[i]; Q += smq[i]; }
        float mean = S * (1.0f / 512.0f);
        float var  = Q * (1.0f / 512.0f) - mean * mean;
        float a = g2[d] * rsqrtf(var + EPSBN);
        par[0] = a; par[1] = b2[d] - mean * a;
    }
    __syncthreads();
    float a = par[0], c = par[1];
    float v0 = fmaf(y0, a, c); v0 = v0 > 0.0f ? v0 : 0.01f * v0;
    float v1 = fmaf(y1, a, c); v1 = v1 > 0.0f ? v1 : 0.01f * v1;
    g_xb[t * KPAD + d]         = __float2bfloat16_rn(v0);
    g_xb[(t + 256) * KPAD + d] = __float2bfloat16_rn(v1);
    if (blockIdx.x == 0) {                 // bias-fold column: X[:,200] = 1.0
        g_xb[t * KPAD + 200]         = __float2bfloat16_rn(1.0f);
        g_xb[(t + 256) * KPAD + 200] = __float2bfloat16_rn(1.0f);
    }
}

// ------------------------------------------------- positive-target scores (512 dots)
__global__ void k_psx(const float* __restrict__ ew, const float* __restrict__ bias,
                      const int* __restrict__ pos) {
    __shared__ double acc8[8];
    int b = blockIdx.x * 8 + (threadIdx.x >> 5);
    int lane = threadIdx.x & 31;
    int p = pos[b];
    const float* e = ew + (size_t)p * DD;
    float s = 0.0f;
    for (int d = lane; d < DD; d += 32)
        s = fmaf(__bfloat162float(g_xb[b * KPAD + d]), e[d], s);
    s = warp_red(s);
    if (lane == 0) acc8[threadIdx.x >> 5] = (double)(s + bias[p]);
    __syncthreads();
    if (threadIdx.x == 0) {
        double S = 0;
        for (int i = 0; i < 8; i++) S += acc8[i];
        atomicAdd(&g_loss[2], S);
    }
}

// ------------------------------------------------- scores: E once, cp.async X pipeline
// Quad-merged softplus: one lg2 per 4 scores via product of (1+t_i).
__global__ __launch_bounds__(256, 2)
void k_scores(const float* __restrict__ ew, const float* __restrict__ bias) {
    extern __shared__ char smem[];
    uint32_t xs = smem_u32(smem);            // X tile: 128 x 216 bf16 = 55296B
    uint32_t es = xs + 55296;                // E tile: 128 x 216 bf16 = 55296B
    __shared__ float red[2][8];
    int t = threadIdx.x, lane = t & 31, wid = t >> 5;
    int NB = blockIdx.x * 128;

    {
        const char* src = (const char*)g_xb;
        for (int i = t; i < 3456; i += 256) CP_ASYNC16(xs + i * 16, src + i * 16);
        CP_COMMIT();
    }
    char* esm = smem + 55296;
    for (int idx = t; idx < 6400; idx += 256) {
        int row = idx / 50, q = idx % 50;
        int e = NB + row;
        uint2 w = make_uint2(0u, 0u);
        if (e < NENT) {
            float4 v = *(const float4*)&ew[(size_t)e * DD + q * 4];
            w = make_uint2(bf2pack(v.x, v.y), bf2pack(v.z, v.w));
        }
        *(uint2*)(esm + row * 432 + q * 8) = w;
    }
    for (int idx = t; idx < 512; idx += 256) {
        int row = idx >> 2, c = idx & 3;
        uint32_t w = 0u;
        if (c == 0) {
            int e = NB + row;
            if (e < NENT)
                w = (uint32_t)__bfloat16_as_ushort(__float2bfloat16_rn(bias[e]));
        }
        *(uint32_t*)(esm + row * 432 + 400 + c * 4) = w;
    }
    CP_WAIT0();
    __syncthreads();

    int mw = wid >> 2, nw = wid & 3;
    int m_base = mw * 64, n_base = nw * 32;
    uint32_t aaddr[4], baddr[2];
#pragma unroll
    for (int mt = 0; mt < 4; mt++)
        aaddr[mt] = xs + (uint32_t)(m_base + mt * 16 + (lane & 15)) * 432 + (lane >> 4) * 16;
#pragma unroll
    for (int p = 0; p < 2; p++)
        baddr[p] = es + (uint32_t)(n_base + p * 16 + (lane >> 4) * 8 + (lane & 7)) * 432
                      + ((lane >> 3) & 1) * 16;

    float spx = 0.0f, ssx = 0.0f;
    const float l2e = 1.4426950408889634f;

    for (int r = 0; r < 4; r++) {
        float acc[4][4][4];
#pragma unroll
        for (int i = 0; i < 4; i++)
#pragma unroll
            for (int j = 0; j < 4; j++)
#pragma unroll
                for (int k = 0; k < 4; k++) acc[i][j][k] = 0.0f;

        for (int ks = 0; ks < 13; ks++) {
            uint32_t A[4][4], Bf[2][4];
#pragma unroll
            for (int mt = 0; mt < 4; mt++) ldm4(A[mt], aaddr[mt] + ks * 32);
#pragma unroll
            for (int p = 0; p < 2; p++)   ldm4(Bf[p], baddr[p] + ks * 32);
#pragma unroll
            for (int mt = 0; mt < 4; mt++)
#pragma unroll
                for (int nt = 0; nt < 4; nt++)
                    mma16816(acc[mt][nt], A[mt], &Bf[nt >> 1][(nt & 1) * 2]);
        }
        __syncthreads();

        if (r < 3) {
            const char* src = (const char*)(g_xb + (r + 1) * 128 * KPAD);
            for (int i = t; i < 3456; i += 256) CP_ASYNC16(xs + i * 16, src + i * 16);
            CP_COMMIT();
        }

        // quad-merged epilogue: per (mt,nt) 4 scores -> 4 ex2 + 1 lg2
#pragma unroll
        for (int mt = 0; mt < 4; mt++)
#pragma unroll
            for (int nt = 0; nt < 4; nt++) {
                float s0 = acc[mt][nt][0], s1 = acc[mt][nt][1];
                float s2 = acc[mt][nt][2], s3 = acc[mt][nt][3];
                ssx += (s0 + s1) + (s2 + s3);
                float t0, t1, t2, t3, lg;
                asm("ex2.approx.f32 %0, %1;" : "=f"(t0) : "f"(-fabsf(s0) * l2e));
                asm("ex2.approx.f32 %0, %1;" : "=f"(t1) : "f"(-fabsf(s1) * l2e));
                asm("ex2.approx.f32 %0, %1;" : "=f"(t2) : "f"(-fabsf(s2) * l2e));
                asm("ex2.approx.f32 %0, %1;" : "=f"(t3) : "f"(-fabsf(s3) * l2e));
                float pr = ((1.0f + t0) * (1.0f + t1)) * ((1.0f + t2) * (1.0f + t3));
                asm("lg2.approx.f32 %0, %1;" : "=f"(lg) : "f"(pr));
                spx += ((fmaxf(s0, 0.0f) + fmaxf(s1, 0.0f))
                      + (fmaxf(s2, 0.0f) + fmaxf(s3, 0.0f)))
                     + 0.69314718055994531f * lg;
            }
        if (r < 3) { CP_WAIT0(); __syncthreads(); }
    }

    spx = warp_red(spx); ssx = warp_red(ssx);
    if (lane == 0) { red[0][wid] = spx; red[1][wid] = ssx; }
    __syncthreads();
    if (t == 0) {
        float SP = 0, SS = 0;
        for (int i = 0; i < 8; i++) { SP += red[0][i]; SS += red[1][i]; }
        atomicAdd(&g_loss[0], (double)SP);
        atomicAdd(&g_loss[1], (double)SS);
    }
}

// ------------------------------------------------- final combine
__global__ void k_final(float* out) {
    double sp = g_loss[0], ss = g_loss[1], ps = g_loss[2];
    // 96 phantom entity rows x 512 batches contribute softplus(0)=ln2 each
    double corr = 49152.0 * 0.69314718055994531;
    double kg = (sp - corr - ss / (double)NENT - 0.9 * ps) / ((double)BATCH * (double)NENT);
    double l2 = g_l2[0] / (2.0 * 512.0 * 200.0)
              + g_l2[1] / (2.0 * 512.0 * 200.0)
              + g_l2[2] / (2.0 * 288.0)
              + g_l2[3] / (2.0 * 200.0);
    out[0] = (float)(kg + 1e-5 * l2);
}

extern "C" void kernel_launch(void* const* d_in, const int* in_sizes, int n_in,
                              void* d_out, int out_size) {
    const float* ew   = (const float*)d_in[0];
    const float* rw   = (const float*)d_in[1];
    const float* cw   = (const float*)d_in[2];
    const float* fcw  = (const float*)d_in[4];
    const float* bias = (const float*)d_in[6];
    const float* g0   = (const float*)d_in[7];
    const float* g1   = (const float*)d_in[9];
    const float* b1   = (const float*)d_in[10];
    const float* g2   = (const float*)d_in[11];
    const float* b2   = (const float*)d_in[12];
    const int*   h    = (const int*)d_in[13];
    const int*   r    = (const int*)d_in[14];
    const int*   pos  = (const int*)d_in[15];

    const int SMEM_SC = 2 * 55296;
    cudaFuncSetAttribute(k_scores, cudaFuncAttributeMaxDynamicSharedMemorySize, SMEM_SC);

    k_init<<<200, 256>>>();
    k_l2w<<<256, 256>>>(fcw, cw);
    k_conv<<<dim3(64, 2), 352>>>(ew, rw, h, r, cw, g0);
    k_fc<<<dim3(8, 2, 18), 256>>>(g1, b1);
    k_bn2<<<200, 256>>>(g2, b2);
    k_psx<<<64, 256>>>(ew, bias, pos);
    k_scores<<<782, 256, SMEM_SC>>>(ew, bias);
    k_final<<<1, 1>>>((float*)d_out);
}

// round 17
// speedup vs baseline: 1.1782x; 1.0454x over previous
#include <cuda_runtime.h>
#include <cuda_bf16.h>
#include <cstdint>

#define NENT  100000
#define BATCH 512
#define DD    200
#define FCIN  10368
#define NCH   32
#define EPSBN 1e-5f
#define KPAD  216            // padded K stride for X image (432B rows)

// g_convb is CHANNEL-MAJOR bf16: element (b, c, p) at [(c*512 + b)*324 + p]
__device__ __nv_bfloat16  g_convb[(size_t)BATCH * FCIN];
__device__ float          g_fc[DD * BATCH];            // TRANSPOSED: [d*512 + b]
__device__ __nv_bfloat16  g_xb[BATCH * KPAD];          // padded bf16 X image (col200 = 1.0)
__device__ __nv_bfloat16  g_fcb[(size_t)256 * FCIN];   // bf16 fc_w (rows >=200 unused)
__device__ double         g_bn1sum[NCH];
__device__ double         g_bn1sq[NCH];
__device__ double         g_l2[4];
__device__ double         g_loss[3];

// ---------------------------------------------------------------- helpers
__device__ __forceinline__ uint32_t smem_u32(const void* p) {
    uint32_t a;
    asm("{ .reg .u64 t; cvta.to.shared.u64 t, %1; cvt.u32.u64 %0, t; }" : "=r"(a) : "l"(p));
    return a;
}
__device__ __forceinline__ void ldm4(uint32_t* r, uint32_t addr) {
    asm volatile("ldmatrix.sync.aligned.m8n8.x4.shared.b16 {%0,%1,%2,%3}, [%4];"
        : "=r"(r[0]), "=r"(r[1]), "=r"(r[2]), "=r"(r[3]) : "r"(addr));
}
__device__ __forceinline__ void mma16816(float* c, const uint32_t* a, const uint32_t* b) {
    asm volatile("mma.sync.aligned.m16n8k16.row.col.f32.bf16.bf16.f32 "
        "{%0,%1,%2,%3}, {%4,%5,%6,%7}, {%8,%9}, {%0,%1,%2,%3};"
        : "+f"(c[0]), "+f"(c[1]), "+f"(c[2]), "+f"(c[3])
        : "r"(a[0]), "r"(a[1]), "r"(a[2]), "r"(a[3]), "r"(b[0]), "r"(b[1]));
}
#define CP_ASYNC16(dst, src) \
    asm volatile("cp.async.cg.shared.global [%0], [%1], 16;" :: "r"(dst), "l"(src))
#define CP_COMMIT() asm volatile("cp.async.commit_group;" ::: "memory")
#define CP_WAIT0()  asm volatile("cp.async.wait_group 0;" ::: "memory")

__device__ __forceinline__ float warp_red(float v) {
#pragma unroll
    for (int o = 16; o > 0; o >>= 1) v += __shfl_down_sync(0xffffffffu, v, o);
    return v;
}
__device__ __forceinline__ uint32_t bf2pack(float a, float b) {
    return ((uint32_t)__bfloat16_as_ushort(__float2bfloat16_rn(b)) << 16)
         |  (uint32_t)__bfloat16_as_ushort(__float2bfloat16_rn(a));
}
// MUFU softplus (k_psx path)
__device__ __forceinline__ float softplus_fast(float s) {
    float e, l;
    float xn = -fabsf(s) * 1.4426950408889634f;
    asm("ex2.approx.f32 %0, %1;" : "=f"(e) : "f"(xn));
    float arg = 1.0f + e;
    asm("lg2.approx.f32 %0, %1;" : "=f"(l) : "f"(arg));
    return fmaxf(s, 0.0f) + 0.69314718055994531f * l;
}

// ---------------------------------------------------------------- init
__global__ void k_init() {
    int idx = blockIdx.x * blockDim.x + threadIdx.x;
    int stride = gridDim.x * blockDim.x;
    for (int i = idx; i < BATCH * DD; i += stride) g_fc[i] = 0.0f;
    uint32_t* xb = (uint32_t*)g_xb;
    for (int i = idx; i < BATCH * KPAD / 2; i += stride) xb[i] = 0u;
    if (idx < NCH) { g_bn1sum[idx] = 0.0; g_bn1sq[idx] = 0.0; }
    if (idx < 4)   g_l2[idx]  = 0.0;
    if (idx < 3)   g_loss[idx] = 0.0;
}

// ------------------------------------------------- fcw L2 + bf16 convert (float4); conv_w L2
__global__ void k_l2w(const float* __restrict__ fcw, const float* __restrict__ cw) {
    __shared__ float sm[8];
    int t = threadIdx.x;
    float loc = 0.0f;
    const float4* src = (const float4*)fcw;
    const int n4 = DD * FCIN / 4;
    for (int i = blockIdx.x * blockDim.x + t; i < n4; i += gridDim.x * blockDim.x) {
        float4 v = src[i];
        loc = fmaf(v.x, v.x, loc); loc = fmaf(v.y, v.y, loc);
        loc = fmaf(v.z, v.z, loc); loc = fmaf(v.w, v.w, loc);
        *(uint2*)&g_fcb[(size_t)i * 4] = make_uint2(bf2pack(v.x, v.y), bf2pack(v.z, v.w));
    }
    loc = warp_red(loc);
    if ((t & 31) == 0) sm[t >> 5] = loc;
    __syncthreads();
    if (t == 0) {
        float S = 0; for (int i = 0; i < 8; i++) S += sm[i];
        atomicAdd(&g_l2[3], (double)S);
    }
    if (blockIdx.x == 0) {
        __syncthreads();
        float lc = 0.0f;
        if (t < NCH * 9) { float v = cw[t]; lc = v * v; }
        lc = warp_red(lc);
        if ((t & 31) == 0) sm[t >> 5] = lc;
        __syncthreads();
        if (t == 0) {
            float S = 0; for (int i = 0; i < 8; i++) S += sm[i];
            atomicAdd(&g_l2[2], (double)S);
        }
    }
}

// ------------------------------------------------- fused gather + emb L2 + conv + bn1 stats
// grid (64, 2): x = 8-batch group, y = 16-channel half. Output bf16.
__global__ void k_conv(const float* __restrict__ ew, const float* __restrict__ rw,
                       const int* __restrict__ h, const int* __restrict__ r,
                       const float* __restrict__ cw, const float* __restrict__ g0p) {
    __shared__ float xn[8][400];
    __shared__ float wts[NCH * 9];
    __shared__ float shh[11], shr[11];
    __shared__ float chs[16], chq[16];
    int b0 = blockIdx.x * 8, t = threadIdx.x;
    int c0 = blockIdx.y * 16;
    float g0 = g0p[0];
    float l2h = 0.0f, l2r = 0.0f;
    for (int i = t; i < 3200; i += 352) {
        int bb = i / 400, pos = i % 400, b = b0 + bb;
        float v;
        if (pos < 200) { v = ew[(size_t)h[b] * DD + pos]; l2h = fmaf(v, v, l2h); }
        else           { v = rw[(size_t)r[b] * DD + (pos - 200)]; l2r = fmaf(v, v, l2r); }
        xn[bb][pos] = g0 * v;
    }
    if (t < NCH * 9) wts[t] = cw[t];
    if (t < 16) { chs[t] = 0.0f; chq[t] = 0.0f; }
    if (blockIdx.y == 0) {
        l2h = warp_red(l2h); l2r = warp_red(l2r);
        if ((t & 31) == 0) { shh[t >> 5] = l2h; shr[t >> 5] = l2r; }
    }
    __syncthreads();
    if (blockIdx.y == 0 && t == 0) {
        float H = 0, R = 0;
        for (int i = 0; i < 11; i++) { H += shh[i]; R += shr[i]; }
        atomicAdd(&g_l2[0], (double)H);
        atomicAdd(&g_l2[1], (double)R);
    }
    bool valid = t < 324;
    int ii = valid ? t / 18 : 0;
    int jj = valid ? t % 18 : 0;
    int boff = ii * 20 + jj;
    for (int c = c0; c < c0 + 16; c++) {
        float s = 0.0f, q = 0.0f;
#pragma unroll
        for (int bb = 0; bb < 8; bb++) {
            const float* base = &xn[bb][boff];
            float acc = 0.0f;
#pragma unroll
            for (int ki = 0; ki < 3; ki++)
#pragma unroll
                for (int kj = 0; kj < 3; kj++)
                    acc = fmaf(base[ki * 20 + kj], wts[c * 9 + ki * 3 + kj], acc);
            if (valid) {
                g_convb[((size_t)c * 512 + b0 + bb) * 324 + t] = __float2bfloat16_rn(acc);
                s += acc;
                q = fmaf(acc, acc, q);
            }
        }
        s = warp_red(s); q = warp_red(q);
        if ((t & 31) == 0) { atomicAdd(&chs[c - c0], s); atomicAdd(&chq[c - c0], q); }
    }
    __syncthreads();
    if (t < 16) {
        atomicAdd(&g_bn1sum[c0 + t], (double)chs[t]);
        atomicAdd(&g_bn1sq[c0 + t],  (double)chq[t]);
    }
}

// ------------------------------------------------- FC via bf16 mma, bf16 A path + hfma2 pack
__global__ __launch_bounds__(256, 2) void k_fc(const float* __restrict__ g1,
                                               const float* __restrict__ b1) {
    __shared__ __align__(16) char As2[2][64 * 144];
    __shared__ __align__(16) char Bs2[2][128 * 144];
    __shared__ __nv_bfloat162 a_tab2[288], b_tab2[288];
    __shared__ float a1s[NCH], b1s[NCH];
    uint32_t as0 = smem_u32(As2[0]);
    uint32_t bs0 = smem_u32(Bs2[0]);
    int t = threadIdx.x, lane = t & 31, wid = t >> 5;
    int m0 = blockIdx.x * 64, n0 = blockIdx.y * 128;
    int kseg = blockIdx.z * 576;
    int arow = t >> 2, aq = t & 3;   // A-pack role: 4 threads per row

    // prefetch B chunk 0 into B0
    {
#pragma unroll
        for (int j = 0; j < 4; j++) {
            int u = t + j * 256;
            int row = u >> 3, off = u & 7;
            CP_ASYNC16(bs0 + row * 144 + off * 16,
                       (const char*)&g_fcb[(size_t)(n0 + row) * FCIN + kseg + off * 8]);
        }
        CP_COMMIT();
    }
    // preload raw bf16 A regs for chunk 0
    uint2 raw[4];
#pragma unroll
    for (int j = 0; j < 4; j++) {
        int k4 = kseg + aq * 16 + j * 4;
        int c = k4 / 324, pp = k4 - c * 324;
        raw[j] = *(const uint2*)&g_convb[((size_t)c * 512 + m0 + arow) * 324 + pp];
    }
    // folded k_bn1fin: bn1 affine from raw sums
    if (t < NCH) {
        double cnt = 512.0 * 324.0;
        double mean = g_bn1sum[t] / cnt;
        double var  = g_bn1sq[t] / cnt - mean * mean;
        float a = g1[t] * rsqrtf((float)var + EPSBN);
        a1s[t] = a;
        b1s[t] = b1[t] - (float)mean * a;
    }
    __syncthreads();
    for (int i = t; i < 288; i += 256) {
        int ka = kseg + 2 * i, kb_ = ka + 1;
        a_tab2[i] = __floats2bfloat162_rn(a1s[ka / 324], a1s[kb_ / 324]);
        b_tab2[i] = __floats2bfloat162_rn(b1s[ka / 324], b1s[kb_ / 324]);
    }
    __syncthreads();

    int mw = wid >> 2, nw = wid & 3;             // 2 x 4 warp layout
    int m_base = mw * 32, n_base = nw * 32;      // warp tile 32m x 32n
    uint32_t aaddr[2], baddr[2];
#pragma unroll
    for (int mt = 0; mt < 2; mt++)
        aaddr[mt] = as0 + (uint32_t)(m_base + mt * 16 + (lane & 15)) * 144 + (lane >> 4) * 16;
#pragma unroll
    for (int p = 0; p < 2; p++)
        baddr[p] = bs0 + (uint32_t)(n_base + p * 16 + (lane >> 4) * 8 + (lane & 7)) * 144
                       + ((lane >> 3) & 1) * 16;

    float acc[2][4][4];
#pragma unroll
    for (int i = 0; i < 2; i++)
#pragma unroll
        for (int j = 0; j < 4; j++)
#pragma unroll
            for (int k = 0; k < 4; k++) acc[i][j][k] = 0.0f;

    const __nv_bfloat162 zero2 = __float2bfloat162_rn(0.0f);
    for (int ch = 0; ch < 9; ch++) {
        int buf = ch & 1;
        int kb = kseg + ch * 64;
        // transform preloaded raw bf16 regs -> A[buf] via hfma2/hmax2
        {
            char* As = As2[buf];
#pragma unroll
            for (int j = 0; j < 4; j++) {
                int kc = aq * 16 + j * 4;
                int kt2 = (ch * 64 + kc) >> 1;
                __nv_bfloat162 x01 = *(__nv_bfloat162*)&raw[j].x;
                __nv_bfloat162 x23 = *(__nv_bfloat162*)&raw[j].y;
                __nv_bfloat162 y01 = __hmax2(__hfma2(x01, a_tab2[kt2],     b_tab2[kt2]),     zero2);
                __nv_bfloat162 y23 = __hmax2(__hfma2(x23, a_tab2[kt2 + 1], b_tab2[kt2 + 1]), zero2);
                uint2 w;
                w.x = *(uint32_t*)&y01;
                w.y = *(uint32_t*)&y23;
                *(uint2*)&As[arow * 144 + kc * 2] = w;
            }
        }
        CP_WAIT0();
        __syncthreads();
        if (ch < 8) {
            int kb2 = kb + 64;
            // next B tile (async)
#pragma unroll
            for (int j = 0; j < 4; j++) {
                int u = t + j * 256;
                int row = u >> 3, off = u & 7;
                CP_ASYNC16(bs0 + (1 - buf) * 18432 + row * 144 + off * 16,
                           (const char*)&g_fcb[(size_t)(n0 + row) * FCIN + kb2 + off * 8]);
            }
            CP_COMMIT();
            // next raw A regs (LDG latency covered by the mma stage below)
#pragma unroll
            for (int j = 0; j < 4; j++) {
                int k4 = kb2 + aq * 16 + j * 4;
                int c = k4 / 324, pp = k4 - c * 324;
                raw[j] = *(const uint2*)&g_convb[((size_t)c * 512 + m0 + arow) * 324 + pp];
            }
        }
        uint32_t ao = buf * 9216, bo = buf * 18432;
#pragma unroll
        for (int ks = 0; ks < 4; ks++) {
            uint32_t A[2][4], Bf[2][4];
#pragma unroll
            for (int mt = 0; mt < 2; mt++) ldm4(A[mt], aaddr[mt] + ao + ks * 32);
#pragma unroll
            for (int p = 0; p < 2; p++)   ldm4(Bf[p], baddr[p] + bo + ks * 32);
#pragma unroll
            for (int mt = 0; mt < 2; mt++)
#pragma unroll
                for (int nt = 0; nt < 4; nt++)
                    mma16816(acc[mt][nt], A[mt], &Bf[nt >> 1][(nt & 1) * 2]);
        }
    }
    // epilogue: atomic accumulate into TRANSPOSED g_fc [d*512 + b]
#pragma unroll
    for (int mt = 0; mt < 2; mt++) {
        int r0 = m0 + m_base + mt * 16 + (lane >> 2);
#pragma unroll
        for (int nt = 0; nt < 4; nt++) {
#pragma unroll
            for (int c2 = 0; c2 < 2; c2++) {
                int d = n0 + n_base + nt * 8 + (lane & 3) * 2 + c2;
                if (d < DD) {
                    atomicAdd(&g_fc[d * 512 + r0],       acc[mt][nt][c2]);
                    atomicAdd(&g_fc[d * 512 + r0 + 8],   acc[mt][nt][2 + c2]);
                }
            }
        }
    }
}

// ------------------------------------------------- bn2 + leaky relu -> padded bf16 X image
__global__ void k_bn2(const float* __restrict__ g2, const float* __restrict__ b2) {
    __shared__ float sms[8], smq[8], par[2];
    int d = blockIdx.x, t = threadIdx.x;
    float y0 = g_fc[d * 512 + t];
    float y1 = g_fc[d * 512 + t + 256];
    float s = y0 + y1;
    float q = fmaf(y0, y0, y1 * y1);
    s = warp_red(s); q = warp_red(q);
    if ((t & 31) == 0) { sms[t >> 5] = s; smq[t >> 5] = q; }
    __syncthreads();
    if (t == 0) {
        float S = 0, Q = 0;
        for (int i = 0; i < 8; i++) { S += sms[i]; Q += smq[i]; }
        float mean = S * (1.0f / 512.0f);
        float var  = Q * (1.0f / 512.0f) - mean * mean;
        float a = g2[d] * rsqrtf(var + EPSBN);
        par[0] = a; par[1] = b2[d] - mean * a;
    }
    __syncthreads();
    float a = par[0], c = par[1];
    float v0 = fmaf(y0, a, c); v0 = v0 > 0.0f ? v0 : 0.01f * v0;
    float v1 = fmaf(y1, a, c); v1 = v1 > 0.0f ? v1 : 0.01f * v1;
    g_xb[t * KPAD + d]         = __float2bfloat16_rn(v0);
    g_xb[(t + 256) * KPAD + d] = __float2bfloat16_rn(v1);
    if (blockIdx.x == 0) {                 // bias-fold column: X[:,200] = 1.0
        g_xb[t * KPAD + 200]         = __float2bfloat16_rn(1.0f);
        g_xb[(t + 256) * KPAD + 200] = __float2bfloat16_rn(1.0f);
    }
}

// ------------------------------------------------- positive-target scores (512 dots)
__global__ void k_psx(const float* __restrict__ ew, const float* __restrict__ bias,
                      const int* __restrict__ pos) {
    __shared__ double acc8[8];
    int b = blockIdx.x * 8 + (threadIdx.x >> 5);
    int lane = threadIdx.x & 31;
    int p = pos[b];
    const float* e = ew + (size_t)p * DD;
    float s = 0.0f;
    for (int d = lane; d < DD; d += 32)
        s = fmaf(__bfloat162float(g_xb[b * KPAD + d]), e[d], s);
    s = warp_red(s);
    if (lane == 0) acc8[threadIdx.x >> 5] = (double)(s + bias[p]);
    __syncthreads();
    if (threadIdx.x == 0) {
        double S = 0;
        for (int i = 0; i < 8; i++) S += acc8[i];
        atomicAdd(&g_loss[2], S);
    }
}

// ------------------------------------------------- scores: E once, cp.async X pipeline
// Quad-merged softplus: one lg2 per 4 scores via product of (1+t_i).
__global__ __launch_bounds__(256, 2)
void k_scores(const float* __restrict__ ew, const float* __restrict__ bias) {
    extern __shared__ char smem[];
    uint32_t xs = smem_u32(smem);            // X tile: 128 x 216 bf16 = 55296B
    uint32_t es = xs + 55296;                // E tile: 128 x 216 bf16 = 55296B
    __shared__ float red[2][8];
    int t = threadIdx.x, lane = t & 31, wid = t >> 5;
    int NB = blockIdx.x * 128;

    {
        const char* src = (const char*)g_xb;
        for (int i = t; i < 3456; i += 256) CP_ASYNC16(xs + i * 16, src + i * 16);
        CP_COMMIT();
    }
    char* esm = smem + 55296;
    for (int idx = t; idx < 6400; idx += 256) {
        int row = idx / 50, q = idx % 50;
        int e = NB + row;
        uint2 w = make_uint2(0u, 0u);
        if (e < NENT) {
            float4 v = *(const float4*)&ew[(size_t)e * DD + q * 4];
            w = make_uint2(bf2pack(v.x, v.y), bf2pack(v.z, v.w));
        }
        *(uint2*)(esm + row * 432 + q * 8) = w;
    }
    for (int idx = t; idx < 512; idx += 256) {
        int row = idx >> 2, c = idx & 3;
        uint32_t w = 0u;
        if (c == 0) {
            int e = NB + row;
            if (e < NENT)
                w = (uint32_t)__bfloat16_as_ushort(__float2bfloat16_rn(bias[e]));
        }
        *(uint32_t*)(esm + row * 432 + 400 + c * 4) = w;
    }
    CP_WAIT0();
    __syncthreads();

    int mw = wid >> 2, nw = wid & 3;
    int m_base = mw * 64, n_base = nw * 32;
    uint32_t aaddr[4], baddr[2];
#pragma unroll
    for (int mt = 0; mt < 4; mt++)
        aaddr[mt] = xs + (uint32_t)(m_base + mt * 16 + (lane & 15)) * 432 + (lane >> 4) * 16;
#pragma unroll
    for (int p = 0; p < 2; p++)
        baddr[p] = es + (uint32_t)(n_base + p * 16 + (lane >> 4) * 8 + (lane & 7)) * 432
                      + ((lane >> 3) & 1) * 16;

    float spx = 0.0f, ssx = 0.0f;
    const float l2e = 1.4426950408889634f;

    for (int r = 0; r < 4; r++) {
        float acc[4][4][4];
#pragma unroll
        for (int i = 0; i < 4; i++)
#pragma unroll
            for (int j = 0; j < 4; j++)
#pragma unroll
                for (int k = 0; k < 4; k++) acc[i][j][k] = 0.0f;

        for (int ks = 0; ks < 13; ks++) {
            uint32_t A[4][4], Bf[2][4];
#pragma unroll
            for (int mt = 0; mt < 4; mt++) ldm4(A[mt], aaddr[mt] + ks * 32);
#pragma unroll
            for (int p = 0; p < 2; p++)   ldm4(Bf[p], baddr[p] + ks * 32);
#pragma unroll
            for (int mt = 0; mt < 4; mt++)
#pragma unroll
                for (int nt = 0; nt < 4; nt++)
                    mma16816(acc[mt][nt], A[mt], &Bf[nt >> 1][(nt & 1) * 2]);
        }
        __syncthreads();

        if (r < 3) {
            const char* src = (const char*)(g_xb + (r + 1) * 128 * KPAD);
            for (int i = t; i < 3456; i += 256) CP_ASYNC16(xs + i * 16, src + i * 16);
            CP_COMMIT();
        }

        // quad-merged epilogue: per (mt,nt) 4 scores -> 4 ex2 + 1 lg2
#pragma unroll
        for (int mt = 0; mt < 4; mt++)
#pragma unroll
            for (int nt = 0; nt < 4; nt++) {
                float s0 = acc[mt][nt][0], s1 = acc[mt][nt][1];
                float s2 = acc[mt][nt][2], s3 = acc[mt][nt][3];
                ssx += (s0 + s1) + (s2 + s3);
                float t0, t1, t2, t3, lg;
                asm("ex2.approx.f32 %0, %1;" : "=f"(t0) : "f"(-fabsf(s0) * l2e));
                asm("ex2.approx.f32 %0, %1;" : "=f"(t1) : "f"(-fabsf(s1) * l2e));
                asm("ex2.approx.f32 %0, %1;" : "=f"(t2) : "f"(-fabsf(s2) * l2e));
                asm("ex2.approx.f32 %0, %1;" : "=f"(t3) : "f"(-fabsf(s3) * l2e));
                float pr = ((1.0f + t0) * (1.0f + t1)) * ((1.0f + t2) * (1.0f + t3));
                asm("lg2.approx.f32 %0, %1;" : "=f"(lg) : "f"(pr));
                spx += ((fmaxf(s0, 0.0f) + fmaxf(s1, 0.0f))
                      + (fmaxf(s2, 0.0f) + fmaxf(s3, 0.0f)))
                     + 0.69314718055994531f * lg;
            }
        if (r < 3) { CP_WAIT0(); __syncthreads(); }
    }

    spx = warp_red(spx); ssx = warp_red(ssx);
    if (lane == 0) { red[0][wid] = spx; red[1][wid] = ssx; }
    __syncthreads();
    if (t == 0) {
        float SP = 0, SS = 0;
        for (int i = 0; i < 8; i++) { SP += red[0][i]; SS += red[1][i]; }
        atomicAdd(&g_loss[0], (double)SP);
        atomicAdd(&g_loss[1], (double)SS);
    }
}

// ------------------------------------------------- final combine
__global__ void k_final(float* out) {
    double sp = g_loss[0], ss = g_loss[1], ps = g_loss[2];
    // 96 phantom entity rows x 512 batches contribute softplus(0)=ln2 each
    double corr = 49152.0 * 0.69314718055994531;
    double kg = (sp - corr - ss / (double)NENT - 0.9 * ps) / ((double)BATCH * (double)NENT);
    double l2 = g_l2[0] / (2.0 * 512.0 * 200.0)
              + g_l2[1] / (2.0 * 512.0 * 200.0)
              + g_l2[2] / (2.0 * 288.0)
              + g_l2[3] / (2.0 * 200.0);
    out[0] = (float)(kg + 1e-5 * l2);
}

extern "C" void kernel_launch(void* const* d_in, const int* in_sizes, int n_in,
                              void* d_out, int out_size) {
    const float* ew   = (const float*)d_in[0];
    const float* rw   = (const float*)d_in[1];
    const float* cw   = (const float*)d_in[2];
    const float* fcw  = (const float*)d_in[4];
    const float* bias = (const float*)d_in[6];
    const float* g0   = (const float*)d_in[7];
    const float* g1   = (const float*)d_in[9];
    const float* b1   = (const float*)d_in[10];
    const float* g2   = (const float*)d_in[11];
    const float* b2   = (const float*)d_in[12];
    const int*   h    = (const int*)d_in[13];
    const int*   r    = (const int*)d_in[14];
    const int*   pos  = (const int*)d_in[15];

    const int SMEM_SC = 2 * 55296;
    cudaFuncSetAttribute(k_scores, cudaFuncAttributeMaxDynamicSharedMemorySize, SMEM_SC);

    k_init<<<200, 256>>>();
    k_l2w<<<256, 256>>>(fcw, cw);
    k_conv<<<dim3(64, 2), 352>>>(ew, rw, h, r, cw, g0);
    k_fc<<<dim3(8, 2, 18), 256>>>(g1, b1);
    k_bn2<<<200, 256>>>(g2, b2);
    k_psx<<<64, 256>>>(ew, bias, pos);
    k_scores<<<782, 256, SMEM_SC>>>(ew, bias);
    k_final<<<1, 1>>>((float*)d_out);
}